// round 2
// baseline (speedup 1.0000x reference)
#include <cuda_runtime.h>

// ---------------- problem constants ----------------
// B=32 graphs, NPG=512 nodes/graph, N=16384, DEG=16 (exactly, contiguous),
// K=64 clusters, ASSIGN=2048, IN=128, HID=EMB=256, PRED_IN=768.

// ---------------- scratch (static device globals; no allocs) ----------------
__device__ float g_hn   [16384*256];      // neighbor-mean scratch (max width 256)
__device__ float g_embG [16384*768];      // [h1|h2|h3]
__device__ float g_a1b  [16384*256];
__device__ float g_a2b  [16384*256];
__device__ float g_a3b  [16384*2048];
__device__ float g_Sb   [16384*64];       // S_local
__device__ float g_ASb  [16384*64];
__device__ float g_hpool[32*64*768];
__device__ float g_hnpool[32*64*768];
__device__ float g_adjb [32*64*64];
__device__ float g_dinvd[32*64];
__device__ float g_pcat [32*64*768];      // [p1|p2|p3]
__device__ float g_pnb  [32*64*256];
__device__ float g_outb [32*1536];
__device__ float g_t1b  [32*256];

// ---------------- neighbor mean/sum over the 16 contiguous in-edges ----------------
// float4 vectorized: D multiple of 4, all buffers 16B aligned.
__global__ void agg16(const float* __restrict__ X, int ldx, int D4,
                      const int* __restrict__ esrc,
                      float* __restrict__ Y, int ldy, float scale) {
    int n = blockIdx.x;
    __shared__ int s[16];
    if (threadIdx.x < 16) s[threadIdx.x] = esrc[n*16 + threadIdx.x];
    __syncthreads();
    for (int d = threadIdx.x; d < D4; d += blockDim.x) {
        float4 acc = make_float4(0.f, 0.f, 0.f, 0.f);
        #pragma unroll
        for (int j = 0; j < 16; ++j) {
            float4 v = *(const float4*)&X[(long)s[j]*ldx + d*4];
            acc.x += v.x; acc.y += v.y; acc.z += v.z; acc.w += v.w;
        }
        acc.x *= scale; acc.y *= scale; acc.z *= scale; acc.w *= scale;
        *(float4*)&Y[(long)n*ldy + d*4] = acc;
    }
}

// ---------------- generic SGEMM: Y = act( [X0|X1] @ W + bias ) ----------------
// 128x128 tile, BK=8, 256 threads, 8x8 microtile. M = gridDim.x*128, cols = gridDim.y*128.
__global__ __launch_bounds__(256) void sgemm2(
    const float* __restrict__ X0, int ld0, int d0,
    const float* __restrict__ X1, int ld1,
    const float* __restrict__ W, int ldw,
    const float* __restrict__ bias,
    float* __restrict__ Y, int ldy, int K, int relu)
{
    __shared__ float As[8][128];
    __shared__ float Bs[8][128];
    int tid = threadIdx.x;
    int tx = tid & 15, ty = tid >> 4;
    int rbase = blockIdx.x * 128;
    int cbase = blockIdx.y * 128;
    float acc[8][8];
    #pragma unroll
    for (int i = 0; i < 8; ++i)
        #pragma unroll
        for (int j = 0; j < 8; ++j) acc[i][j] = 0.f;

    int arow = tid >> 1;            // 0..127
    int ak0  = (tid & 1) * 4;       // 0 or 4
    int bk   = tid >> 5;            // 0..7
    int bc   = (tid & 31) * 4;      // 0..124

    for (int k0 = 0; k0 < K; k0 += 8) {
        int row = rbase + arow;
        #pragma unroll
        for (int i = 0; i < 4; ++i) {
            int k = k0 + ak0 + i;
            float v = (k < d0) ? X0[(long)row*ld0 + k]
                               : X1[(long)row*ld1 + (k - d0)];
            As[ak0 + i][arow] = v;
        }
        float4 bv = *(const float4*)&W[(long)(k0 + bk)*ldw + cbase + bc];
        *(float4*)&Bs[bk][bc] = bv;
        __syncthreads();
        #pragma unroll
        for (int kk = 0; kk < 8; ++kk) {
            float4 a0 = *(const float4*)&As[kk][ty*8];
            float4 a1 = *(const float4*)&As[kk][ty*8 + 4];
            float4 b0 = *(const float4*)&Bs[kk][tx*8];
            float4 b1 = *(const float4*)&Bs[kk][tx*8 + 4];
            float a[8] = {a0.x,a0.y,a0.z,a0.w,a1.x,a1.y,a1.z,a1.w};
            float b[8] = {b0.x,b0.y,b0.z,b0.w,b1.x,b1.y,b1.z,b1.w};
            #pragma unroll
            for (int i = 0; i < 8; ++i)
                #pragma unroll
                for (int j = 0; j < 8; ++j) acc[i][j] += a[i]*b[j];
        }
        __syncthreads();
    }
    #pragma unroll
    for (int i = 0; i < 8; ++i) {
        int row = rbase + ty*8 + i;
        #pragma unroll
        for (int j = 0; j < 8; ++j) {
            int col = cbase + tx*8 + j;
            float v = acc[i][j] + bias[col];
            if (relu) v = fmaxf(v, 0.f);
            Y[(long)row*ldy + col] = v;
        }
    }
}

// ---------------- per-graph logits (64 cols of pW) + fused masked softmax ----------------
// grid (16, 32): blockIdx.y = graph g, blockIdx.x = 32-row tile. K = 2560 = [a1(256)|a2(256)|a3(2048)].
__global__ __launch_bounds__(256) void logits_softmax(
    const float* __restrict__ A1, const float* __restrict__ A2,
    const float* __restrict__ A3, const float* __restrict__ pW,
    const float* __restrict__ pb, float* __restrict__ S)
{
    int g = blockIdx.y;
    int r0 = g*512 + blockIdx.x*32;
    __shared__ float Xs[32][64];
    __shared__ float Ws[64][64];
    __shared__ float L[32][65];
    int tid = threadIdx.x;
    int c = tid & 63, rq = tid >> 6;   // c: col 0..63, rq: 8-row group 0..3
    float acc[8];
    #pragma unroll
    for (int r = 0; r < 8; ++r) acc[r] = 0.f;

    for (int k0 = 0; k0 < 2560; k0 += 64) {
        #pragma unroll
        for (int i = 0; i < 8; ++i) {
            int e = tid + i*256; int r = e >> 6, kk = e & 63;
            int k = k0 + kk; int row = r0 + r;
            float v;
            if (k < 256)      v = A1[(long)row*256 + k];
            else if (k < 512) v = A2[(long)row*256 + (k - 256)];
            else              v = A3[(long)row*2048 + (k - 512)];
            Xs[r][kk] = v;
        }
        #pragma unroll
        for (int i = 0; i < 16; ++i) {
            int e = tid + i*256; int kk = e >> 6, cc = e & 63;
            Ws[kk][cc] = pW[(long)(k0 + kk)*2048 + g*64 + cc];
        }
        __syncthreads();
        #pragma unroll 4
        for (int kk = 0; kk < 64; kk += 4) {
            float w0 = Ws[kk][c], w1 = Ws[kk+1][c], w2 = Ws[kk+2][c], w3 = Ws[kk+3][c];
            #pragma unroll
            for (int r = 0; r < 8; ++r) {
                float4 x = *(const float4*)&Xs[rq*8 + r][kk];
                acc[r] += x.x*w0 + x.y*w1 + x.z*w2 + x.w*w3;
            }
        }
        __syncthreads();
    }
    float bias = pb[g*64 + c];
    #pragma unroll
    for (int r = 0; r < 8; ++r) L[rq*8 + r][c] = acc[r] + bias;
    __syncthreads();

    // softmax over 64 cols: 8 warps x 4 rows
    int w = tid >> 5, lane = tid & 31;
    for (int rr = 0; rr < 4; ++rr) {
        int row = w*4 + rr;
        float v0 = L[row][lane], v1 = L[row][lane + 32];
        float m = fmaxf(v0, v1);
        #pragma unroll
        for (int o = 16; o > 0; o >>= 1) m = fmaxf(m, __shfl_xor_sync(0xffffffffu, m, o));
        float e0 = __expf(v0 - m), e1 = __expf(v1 - m);
        float s = e0 + e1;
        #pragma unroll
        for (int o = 16; o > 0; o >>= 1) s += __shfl_xor_sync(0xffffffffu, s, o);
        float inv = 1.f / s;
        long base = (long)(r0 + row)*64;
        S[base + lane]      = e0*inv;
        S[base + lane + 32] = e1*inv;
    }
}

// ---------------- per-graph S^T @ X : out[b,k,d] = sum_n S[b,n,k] X[b,n,d] ----------------
// grid (D/64, 32). 64x64 output tile, 256 threads, 4x4 microtile.
__global__ __launch_bounds__(256) void atb64(
    const float* __restrict__ Sp, const float* __restrict__ X, int ldx,
    float* __restrict__ O, int ldo)
{
    int b = blockIdx.y; int d0 = blockIdx.x*64;
    __shared__ float Ss[32][64];
    __shared__ float Xs[32][64];
    int tid = threadIdx.x;
    int tx = tid & 15, ty = tid >> 4;
    float acc[4][4];
    #pragma unroll
    for (int i = 0; i < 4; ++i)
        #pragma unroll
        for (int j = 0; j < 4; ++j) acc[i][j] = 0.f;

    for (int n0 = 0; n0 < 512; n0 += 32) {
        #pragma unroll
        for (int i = 0; i < 8; ++i) {
            int e = tid + i*256; int n = e >> 6, k = e & 63;
            int row = b*512 + n0 + n;
            Ss[n][k] = Sp[(long)row*64 + k];
            Xs[n][k] = X[(long)row*ldx + d0 + k];
        }
        __syncthreads();
        #pragma unroll
        for (int n = 0; n < 32; ++n) {
            float4 av = *(const float4*)&Ss[n][ty*4];
            float4 bv = *(const float4*)&Xs[n][tx*4];
            float a[4] = {av.x,av.y,av.z,av.w};
            float bb[4] = {bv.x,bv.y,bv.z,bv.w};
            #pragma unroll
            for (int i = 0; i < 4; ++i)
                #pragma unroll
                for (int j = 0; j < 4; ++j) acc[i][j] += a[i]*bb[j];
        }
        __syncthreads();
    }
    #pragma unroll
    for (int i = 0; i < 4; ++i) {
        int k = ty*4 + i;
        #pragma unroll
        for (int j = 0; j < 4; ++j)
            O[(long)(b*64 + k)*ldo + d0 + tx*4 + j] = acc[i][j];
    }
}

// ---------------- adj row-sums -> 1/(sum+1e-9) ----------------
__global__ void rowsum_k() {
    int i = blockIdx.x*blockDim.x + threadIdx.x;   // 0..2047 = (b,u)
    float s = 0.f;
    #pragma unroll 8
    for (int l = 0; l < 64; ++l) s += g_adjb[i*64 + l];
    g_dinvd[i] = 1.f / (s + 1e-9f);
}

// ---------------- hn = dinvd * (adj @ H)   per graph ----------------
// grid (D/64, 32), 256 threads: 64 u x 4 d-groups of 16.
__global__ __launch_bounds__(256) void adjmm(
    const float* __restrict__ H, int ldh, float* __restrict__ O, int ldo)
{
    int b = blockIdx.y; int d0 = blockIdx.x*64;
    __shared__ float Aj[64][65];
    __shared__ float Hs[64][65];
    int tid = threadIdx.x;
    #pragma unroll
    for (int i = 0; i < 16; ++i) {
        int e = tid + i*256; int u = e >> 6, v = e & 63;
        Aj[u][v] = g_adjb[b*4096 + e];
        Hs[u][v] = H[(long)(b*64 + u)*ldh + d0 + v];
    }
    __syncthreads();
    int u = tid & 63, dg = tid >> 6;    // dg 0..3
    float acc[16];
    #pragma unroll
    for (int i = 0; i < 16; ++i) acc[i] = 0.f;
    for (int v = 0; v < 64; ++v) {
        float a = Aj[u][v];
        #pragma unroll
        for (int i = 0; i < 16; ++i) acc[i] += a * Hs[v][dg*16 + i];
    }
    float s = g_dinvd[b*64 + u];
    #pragma unroll
    for (int i = 0; i < 16; ++i)
        O[(long)(b*64 + u)*ldo + d0 + dg*16 + i] = acc[i]*s;
}

// ---------------- max-pool over R rows per graph ----------------
__global__ void maxpool(const float* __restrict__ X, int ld, int R, int D,
                        float* __restrict__ Y, int ldy) {
    int b = blockIdx.x;
    int d = blockIdx.y*blockDim.x + threadIdx.x;
    if (d >= D) return;
    const float* p = X + (long)b*R*ld + d;
    float m = -3.402823466e38f;
    for (int r = 0; r < R; ++r) m = fmaxf(m, p[(long)r*ld]);
    Y[(long)b*ldy + d] = m;
}

// ---------------- final MLP ----------------
__global__ void mlp1k(const float* __restrict__ X, const float* __restrict__ W,
                      const float* __restrict__ b, float* __restrict__ Y) {
    int row = blockIdx.x, c = threadIdx.x;           // 32 x 256
    float acc = b[c];
    for (int k = 0; k < 1536; ++k) acc += X[row*1536 + k] * W[k*256 + c];
    Y[row*256 + c] = acc;
}
__global__ void mlp2k(const float* __restrict__ X, const float* __restrict__ W,
                      const float* __restrict__ b, float* __restrict__ Y) {
    int i = threadIdx.x;
    if (i >= 320) return;
    int r = i / 10, j = i % 10;
    float acc = b[j];
    for (int k = 0; k < 256; ++k) acc += X[r*256 + k] * W[k*10 + j];
    Y[i] = acc;
}

// ---------------- launch ----------------
extern "C" void kernel_launch(void* const* d_in, const int* in_sizes, int n_in,
                              void* d_out, int out_size) {
    const float* feat = (const float*)d_in[0];
    const int*   esrc = (const int*)  d_in[1];
    const float *W1=(const float*)d_in[3],  *b1=(const float*)d_in[4];
    const float *W2=(const float*)d_in[5],  *b2=(const float*)d_in[6];
    const float *W3=(const float*)d_in[7],  *b3=(const float*)d_in[8];
    const float *aW1=(const float*)d_in[9], *ab1=(const float*)d_in[10];
    const float *aW2=(const float*)d_in[11],*ab2=(const float*)d_in[12];
    const float *aW3=(const float*)d_in[13],*ab3=(const float*)d_in[14];
    const float *pW=(const float*)d_in[15], *pb=(const float*)d_in[16];
    const float *qW1=(const float*)d_in[17],*qb1=(const float*)d_in[18];
    const float *qW2=(const float*)d_in[19],*qb2=(const float*)d_in[20];
    const float *qW3=(const float*)d_in[21],*qb3=(const float*)d_in[22];
    const float *mW1=(const float*)d_in[23],*mb1=(const float*)d_in[24];
    const float *mW2=(const float*)d_in[25],*mb2=(const float*)d_in[26];

    // One-time symbol-address lookup (device globals have fixed addresses;
    // deterministic, avoids runtime API calls inside graph capture).
    static float *hn=nullptr, *emb, *a1, *a2, *a3, *S, *AS, *hpool, *hnpool,
                 *adjp, *pcat, *pn, *outb, *t1;
    if (!hn) {
        cudaGetSymbolAddress((void**)&hn,    g_hn);
        cudaGetSymbolAddress((void**)&emb,   g_embG);
        cudaGetSymbolAddress((void**)&a1,    g_a1b);
        cudaGetSymbolAddress((void**)&a2,    g_a2b);
        cudaGetSymbolAddress((void**)&a3,    g_a3b);
        cudaGetSymbolAddress((void**)&S,     g_Sb);
        cudaGetSymbolAddress((void**)&AS,    g_ASb);
        cudaGetSymbolAddress((void**)&hpool, g_hpool);
        cudaGetSymbolAddress((void**)&hnpool,g_hnpool);
        cudaGetSymbolAddress((void**)&adjp,  g_adjb);
        cudaGetSymbolAddress((void**)&pcat,  g_pcat);
        cudaGetSymbolAddress((void**)&pn,    g_pnb);
        cudaGetSymbolAddress((void**)&outb,  g_outb);
        cudaGetSymbolAddress((void**)&t1,    g_t1b);
    }

    const float inv16 = 1.f/16.f;

    // --- pre-pool GC stack + assignment stack ---
    agg16<<<16384,128>>>(feat,128,32, esrc, hn,128, inv16);                       // hn0
    sgemm2<<<dim3(128,2),256>>>(feat,128,128, hn,128, W1,256,  b1,  emb,     768, 256, 1);  // h1
    sgemm2<<<dim3(128,2),256>>>(feat,128,128, hn,128, aW1,256, ab1, a1,      256, 256, 1);  // a1
    agg16<<<16384,128>>>(emb,768,64, esrc, hn,256, inv16);
    sgemm2<<<dim3(128,2),256>>>(emb,768,256, hn,256, W2,256,  b2,  emb+256, 768, 512, 1);  // h2
    agg16<<<16384,128>>>(emb+256,768,64, esrc, hn,256, inv16);
    sgemm2<<<dim3(128,2),256>>>(emb+256,768,256, hn,256, W3,256, b3, emb+512, 768, 512, 0); // h3
    agg16<<<16384,128>>>(a1,256,64, esrc, hn,256, inv16);
    sgemm2<<<dim3(128,2),256>>>(a1,256,256, hn,256, aW2,256, ab2, a2,       256, 512, 1);  // a2
    agg16<<<16384,128>>>(a2,256,64, esrc, hn,256, inv16);
    sgemm2<<<dim3(128,16),256>>>(a2,256,256, hn,256, aW3,2048, ab3, a3,    2048, 512, 1);  // a3

    // --- block-diagonal logits + masked softmax ---
    logits_softmax<<<dim3(16,32),256>>>(a1, a2, a3, pW, pb, S);

    // --- readout 1 ---
    maxpool<<<dim3(32,3),256>>>(emb,768, 512, 768, outb, 1536);

    // --- pooling: h_pool = S^T X, AS, adj = S^T AS ---
    atb64<<<dim3(12,32),256>>>(S, emb,768, hpool,768);
    agg16<<<16384,64>>>(S,64,16, esrc, AS,64, 1.f);
    atb64<<<dim3(1,32),256>>>(S, AS,64, adjp,64);
    rowsum_k<<<8,256>>>();

    // --- dense SAGE stack on pooled graph ---
    adjmm<<<dim3(12,32),256>>>(hpool,768, hnpool,768);
    sgemm2<<<dim3(16,2),256>>>(hpool,768,768, hnpool,768, qW1,256, qb1, pcat,     768, 1536, 1); // p1
    adjmm<<<dim3(4,32),256>>>(pcat,768, pn,256);
    sgemm2<<<dim3(16,2),256>>>(pcat,768,256, pn,256, qW2,256, qb2, pcat+256, 768, 512, 1);       // p2
    adjmm<<<dim3(4,32),256>>>(pcat+256,768, pn,256);
    sgemm2<<<dim3(16,2),256>>>(pcat+256,768,256, pn,256, qW3,256, qb3, pcat+512, 768, 512, 0);   // p3

    // --- readout 2 + prediction MLP ---
    maxpool<<<dim3(32,3),256>>>(pcat,768, 64, 768, outb+768, 1536);
    mlp1k<<<32,256>>>(outb, mW1, mb1, t1);
    mlp2k<<<1,320>>>(t1, mW2, mb2, (float*)d_out);
}

// round 3
// speedup vs baseline: 1.7520x; 1.7520x over previous
#include <cuda_runtime.h>
#include <cuda_bf16.h>
#include <cstdint>

typedef __nv_bfloat16 bf16;

// ---------------- problem constants ----------------
// B=32, NPG=512, N=16384, DEG=16 (exact, contiguous), K=64, ASSIGN=2048,
// IN=128, HID=EMB=256, PRED_IN=768.

// ---------------- scratch (static device globals; no allocs) ----------------
__device__ float g_ecat [16384*768];      // [h1|h2|h3] fp32
__device__ float g_a1f  [16384*256];
__device__ float g_a2f  [16384*256];
__device__ float g_Sb   [16384*64];
__device__ float g_ASb  [16384*64];
__device__ float g_hpool[32*64*768];
__device__ float g_hnpool[32*64*768];
__device__ float g_adjb [32*64*64];
__device__ float g_dinvd[32*64];
__device__ float g_pcat [32*64*768];
__device__ float g_pnb  [32*64*256];
__device__ float g_outb [32*1536];
__device__ float g_t1b  [32*256];
// bf16 hi/lo activation buffers
__device__ bf16 g_fh[16384*128],   g_fl[16384*128];
__device__ bf16 g_hnh[16384*256],  g_hnl[16384*256];
__device__ bf16 g_eh[16384*512],   g_el[16384*512];      // [h1|h2]
__device__ bf16 g_ach[16384*2560], g_acl[16384*2560];    // [a1|a2|a3]
// bf16 hi/lo weight buffers
__device__ bf16 g_W1h[65536],  g_W1l[65536];
__device__ bf16 g_W2h[131072], g_W2l[131072];
__device__ bf16 g_W3h[131072], g_W3l[131072];
__device__ bf16 g_aW1h[65536], g_aW1l[65536];
__device__ bf16 g_aW2h[131072],g_aW2l[131072];
__device__ bf16 g_aW3h[1048576], g_aW3l[1048576];
__device__ bf16 g_pWh[5242880], g_pWl[5242880];

// ---------------- helpers ----------------
__device__ __forceinline__ uint32_t smaddr(const void* p) {
    return (uint32_t)__cvta_generic_to_shared(p);
}
__device__ __forceinline__ void ldsm4(uint32_t r[4], uint32_t a) {
    asm volatile("ldmatrix.sync.aligned.m8n8.x4.shared.b16 {%0,%1,%2,%3},[%4];"
                 : "=r"(r[0]),"=r"(r[1]),"=r"(r[2]),"=r"(r[3]) : "r"(a));
}
__device__ __forceinline__ void ldsm4t(uint32_t r[4], uint32_t a) {
    asm volatile("ldmatrix.sync.aligned.m8n8.x4.trans.shared.b16 {%0,%1,%2,%3},[%4];"
                 : "=r"(r[0]),"=r"(r[1]),"=r"(r[2]),"=r"(r[3]) : "r"(a));
}
__device__ __forceinline__ void mma16816(float c[4], const uint32_t a[4], const uint32_t b[2]) {
    asm volatile("mma.sync.aligned.m16n8k16.row.col.f32.bf16.bf16.f32 "
                 "{%0,%1,%2,%3},{%4,%5,%6,%7},{%8,%9},{%0,%1,%2,%3};"
                 : "+f"(c[0]),"+f"(c[1]),"+f"(c[2]),"+f"(c[3])
                 : "r"(a[0]),"r"(a[1]),"r"(a[2]),"r"(a[3]),"r"(b[0]),"r"(b[1]));
}
__device__ __forceinline__ uint32_t pack_bf2(float a, float b) {
    __nv_bfloat162 t; t.x = __float2bfloat16(a); t.y = __float2bfloat16(b);
    return *reinterpret_cast<uint32_t*>(&t);
}

// ---------------- fp32 -> (hi,lo) bf16 split (vectorized x4) ----------------
__global__ void splitv4(const float* __restrict__ x, bf16* __restrict__ h,
                        bf16* __restrict__ l, int n4) {
    int i = blockIdx.x*blockDim.x + threadIdx.x;
    if (i >= n4) return;
    float4 v = ((const float4*)x)[i];
    bf16 h0=__float2bfloat16(v.x), h1=__float2bfloat16(v.y),
         h2=__float2bfloat16(v.z), h3=__float2bfloat16(v.w);
    float l0=v.x-__bfloat162float(h0), l1=v.y-__bfloat162float(h1),
          l2=v.z-__bfloat162float(h2), l3=v.w-__bfloat162float(h3);
    uint2 H, L;
    H.x = pack_bf2(__bfloat162float(h0), __bfloat162float(h1));
    H.y = pack_bf2(__bfloat162float(h2), __bfloat162float(h3));
    L.x = pack_bf2(l0, l1); L.y = pack_bf2(l2, l3);
    ((uint2*)h)[i] = H; ((uint2*)l)[i] = L;
}

// ---------------- neighbor mean over 16 contiguous in-edges -> hi/lo bf16 ----------------
__global__ void agg16_split(const float* __restrict__ X, int ldx, int D4,
                            const int* __restrict__ esrc,
                            bf16* __restrict__ Yh, bf16* __restrict__ Yl,
                            int ldy, float scale) {
    int n = blockIdx.x;
    __shared__ int s[16];
    if (threadIdx.x < 16) s[threadIdx.x] = esrc[n*16 + threadIdx.x];
    __syncthreads();
    for (int d = threadIdx.x; d < D4; d += blockDim.x) {
        float4 acc = make_float4(0.f,0.f,0.f,0.f);
        #pragma unroll
        for (int j = 0; j < 16; ++j) {
            float4 v = *(const float4*)&X[(long)s[j]*ldx + d*4];
            acc.x += v.x; acc.y += v.y; acc.z += v.z; acc.w += v.w;
        }
        acc.x *= scale; acc.y *= scale; acc.z *= scale; acc.w *= scale;
        bf16 h0=__float2bfloat16(acc.x), h1=__float2bfloat16(acc.y),
             h2=__float2bfloat16(acc.z), h3=__float2bfloat16(acc.w);
        uint2 H, L;
        H.x = pack_bf2(__bfloat162float(h0), __bfloat162float(h1));
        H.y = pack_bf2(__bfloat162float(h2), __bfloat162float(h3));
        L.x = pack_bf2(acc.x-__bfloat162float(h0), acc.y-__bfloat162float(h1));
        L.y = pack_bf2(acc.z-__bfloat162float(h2), acc.w-__bfloat162float(h3));
        *(uint2*)&Yh[(long)n*ldy + d*4] = H;
        *(uint2*)&Yl[(long)n*ldy + d*4] = L;
    }
}

// ---------------- fp32 neighbor sum (for AS) ----------------
__global__ void agg16(const float* __restrict__ X, int ldx, int D4,
                      const int* __restrict__ esrc,
                      float* __restrict__ Y, int ldy, float scale) {
    int n = blockIdx.x;
    __shared__ int s[16];
    if (threadIdx.x < 16) s[threadIdx.x] = esrc[n*16 + threadIdx.x];
    __syncthreads();
    for (int d = threadIdx.x; d < D4; d += blockDim.x) {
        float4 acc = make_float4(0.f,0.f,0.f,0.f);
        #pragma unroll
        for (int j = 0; j < 16; ++j) {
            float4 v = *(const float4*)&X[(long)s[j]*ldx + d*4];
            acc.x += v.x; acc.y += v.y; acc.z += v.z; acc.w += v.w;
        }
        acc.x *= scale; acc.y *= scale; acc.z *= scale; acc.w *= scale;
        *(float4*)&Y[(long)n*ldy + d*4] = acc;
    }
}

// ---------------- 3-pass bf16 tensor-core GEMM ----------------
// Y = act([X0|X1] @ W + bias), X/W given as hi/lo bf16. 128x128x32 tiles,
// 8 warps (2 Mwarps x 4 Nwarps), warp tile 64x32. d0 and K multiples of 32.
__global__ __launch_bounds__(256) void bgemm(
    const bf16* __restrict__ X0h, const bf16* __restrict__ X0l, int ld0, int d0,
    const bf16* __restrict__ X1h, const bf16* __restrict__ X1l, int ld1,
    const bf16* __restrict__ Wh,  const bf16* __restrict__ Wl,  int ldw,
    const float* __restrict__ bias,
    float* __restrict__ Yf, int ldyf,
    bf16* __restrict__ Yh, bf16* __restrict__ Yl, int ldy,
    int K, int relu)
{
    __shared__ bf16 Ah[128][40], Al[128][40];
    __shared__ bf16 Bh[32][136], Bl[32][136];
    int tid = threadIdx.x, warp = tid>>5, lane = tid&31;
    int wm = warp>>2, wn = warp&3;
    int rbase = blockIdx.x*128, cbase = blockIdx.y*128;
    float acc[4][4][4];
    #pragma unroll
    for (int i=0;i<4;i++) for (int j=0;j<4;j++) for (int k=0;k<4;k++) acc[i][j][k]=0.f;

    int arow = tid>>1, aseg = (tid&1)*16;
    int brow = tid>>3, bseg = (tid&7)*16;

    for (int kt = 0; kt < K; kt += 32) {
        const bf16 *sh, *sl; int ldx, kk;
        if (kt < d0) { sh=X0h; sl=X0l; ldx=ld0; kk=kt; }
        else         { sh=X1h; sl=X1l; ldx=ld1; kk=kt-d0; }
        long ab = (long)(rbase+arow)*ldx + kk + aseg;
        *(uint4*)&Ah[arow][aseg]   = *(const uint4*)(sh+ab);
        *(uint4*)&Ah[arow][aseg+8] = *(const uint4*)(sh+ab+8);
        *(uint4*)&Al[arow][aseg]   = *(const uint4*)(sl+ab);
        *(uint4*)&Al[arow][aseg+8] = *(const uint4*)(sl+ab+8);
        long bb = (long)(kt+brow)*ldw + cbase + bseg;
        *(uint4*)&Bh[brow][bseg]   = *(const uint4*)(Wh+bb);
        *(uint4*)&Bh[brow][bseg+8] = *(const uint4*)(Wh+bb+8);
        *(uint4*)&Bl[brow][bseg]   = *(const uint4*)(Wl+bb);
        *(uint4*)&Bl[brow][bseg+8] = *(const uint4*)(Wl+bb+8);
        __syncthreads();
        #pragma unroll
        for (int ks = 0; ks < 2; ++ks) {
            int kc = ks*16;
            uint32_t afh[4][4], afl[4][4], bfh[4][2], bfl[4][2];
            #pragma unroll
            for (int mt = 0; mt < 4; ++mt) {
                int row = wm*64 + mt*16 + (lane&15), col = kc + (lane>>4)*8;
                ldsm4(afh[mt], smaddr(&Ah[row][col]));
                ldsm4(afl[mt], smaddr(&Al[row][col]));
            }
            #pragma unroll
            for (int np = 0; np < 2; ++np) {
                int row = kc + (lane&15), col = wn*32 + np*16 + (lane>>4)*8;
                uint32_t t[4];
                ldsm4t(t, smaddr(&Bh[row][col]));
                bfh[np*2][0]=t[0]; bfh[np*2][1]=t[1]; bfh[np*2+1][0]=t[2]; bfh[np*2+1][1]=t[3];
                ldsm4t(t, smaddr(&Bl[row][col]));
                bfl[np*2][0]=t[0]; bfl[np*2][1]=t[1]; bfl[np*2+1][0]=t[2]; bfl[np*2+1][1]=t[3];
            }
            #pragma unroll
            for (int mt = 0; mt < 4; ++mt)
                #pragma unroll
                for (int nt = 0; nt < 4; ++nt) {
                    mma16816(acc[mt][nt], afh[mt], bfh[nt]);
                    mma16816(acc[mt][nt], afh[mt], bfl[nt]);
                    mma16816(acc[mt][nt], afl[mt], bfh[nt]);
                }
        }
        __syncthreads();
    }
    // epilogue
    int q = lane>>2, r4 = lane&3;
    #pragma unroll
    for (int mt = 0; mt < 4; ++mt) {
        #pragma unroll
        for (int nt = 0; nt < 4; ++nt) {
            int c0 = cbase + wn*32 + nt*8 + r4*2;
            float b0 = bias[c0], b1 = bias[c0+1];
            #pragma unroll
            for (int h = 0; h < 2; ++h) {
                int row = rbase + wm*64 + mt*16 + q + h*8;
                float v0 = acc[mt][nt][h*2]   + b0;
                float v1 = acc[mt][nt][h*2+1] + b1;
                if (relu) { v0 = fmaxf(v0,0.f); v1 = fmaxf(v1,0.f); }
                if (Yf) *(float2*)&Yf[(long)row*ldyf + c0] = make_float2(v0, v1);
                if (Yh) {
                    bf16 h0=__float2bfloat16(v0), h1=__float2bfloat16(v1);
                    *(uint32_t*)&Yh[(long)row*ldy + c0] =
                        pack_bf2(__bfloat162float(h0), __bfloat162float(h1));
                    *(uint32_t*)&Yl[(long)row*ldy + c0] =
                        pack_bf2(v0-__bfloat162float(h0), v1-__bfloat162float(h1));
                }
            }
        }
    }
}

// ---------------- per-graph logits GEMM + fused masked softmax ----------------
// grid (4, 32): by = graph, bx = 128-row tile. A = acat [N,2560] hi/lo,
// B = pW[:, g*64 .. g*64+63] hi/lo. Warp tile 16M x 64N (8 warps).
__global__ __launch_bounds__(256) void logits_mma(
    const bf16* __restrict__ Ah_, const bf16* __restrict__ Al_,
    const bf16* __restrict__ pWh, const bf16* __restrict__ pWl,
    const float* __restrict__ pb, float* __restrict__ S)
{
    __shared__ bf16 Ah[128][40], Al[128][40];
    __shared__ bf16 Bh[32][72],  Bl[32][72];
    int g = blockIdx.y;
    int r0 = g*512 + blockIdx.x*128;
    int tid = threadIdx.x, warp = tid>>5, lane = tid&31;
    float acc[8][4];
    #pragma unroll
    for (int i=0;i<8;i++) for (int j=0;j<4;j++) acc[i][j]=0.f;

    int arow = tid>>1, aseg = (tid&1)*16;
    int brow = tid>>3, bseg = (tid&7)*8;

    for (int kt = 0; kt < 2560; kt += 32) {
        long ab = (long)(r0+arow)*2560 + kt + aseg;
        *(uint4*)&Ah[arow][aseg]   = *(const uint4*)(Ah_+ab);
        *(uint4*)&Ah[arow][aseg+8] = *(const uint4*)(Ah_+ab+8);
        *(uint4*)&Al[arow][aseg]   = *(const uint4*)(Al_+ab);
        *(uint4*)&Al[arow][aseg+8] = *(const uint4*)(Al_+ab+8);
        long bb = (long)(kt+brow)*2048 + g*64 + bseg;
        *(uint4*)&Bh[brow][bseg] = *(const uint4*)(pWh+bb);
        *(uint4*)&Bl[brow][bseg] = *(const uint4*)(pWl+bb);
        __syncthreads();
        #pragma unroll
        for (int ks = 0; ks < 2; ++ks) {
            int kc = ks*16;
            uint32_t afh[4], afl[4], bfh[8][2], bfl[8][2];
            int row = warp*16 + (lane&15), col = kc + (lane>>4)*8;
            ldsm4(afh, smaddr(&Ah[row][col]));
            ldsm4(afl, smaddr(&Al[row][col]));
            #pragma unroll
            for (int np = 0; np < 4; ++np) {
                int br = kc + (lane&15), bc = np*16 + (lane>>4)*8;
                uint32_t t[4];
                ldsm4t(t, smaddr(&Bh[br][bc]));
                bfh[np*2][0]=t[0]; bfh[np*2][1]=t[1]; bfh[np*2+1][0]=t[2]; bfh[np*2+1][1]=t[3];
                ldsm4t(t, smaddr(&Bl[br][bc]));
                bfl[np*2][0]=t[0]; bfl[np*2][1]=t[1]; bfl[np*2+1][0]=t[2]; bfl[np*2+1][1]=t[3];
            }
            #pragma unroll
            for (int nt = 0; nt < 8; ++nt) {
                mma16816(acc[nt], afh, bfh[nt]);
                mma16816(acc[nt], afh, bfl[nt]);
                mma16816(acc[nt], afl, bfh[nt]);
            }
        }
        __syncthreads();
    }
    // fused softmax over 64 cols; rows owned per-warp, reduce across quad (lane&3)
    int q = lane>>2, r4 = lane&3;
    #pragma unroll
    for (int nt = 0; nt < 8; ++nt) {
        int c = g*64 + nt*8 + r4*2;
        float b0 = pb[c], b1 = pb[c+1];
        acc[nt][0]+=b0; acc[nt][1]+=b1; acc[nt][2]+=b0; acc[nt][3]+=b1;
    }
    #pragma unroll
    for (int h = 0; h < 2; ++h) {
        float m = -3.402823466e38f;
        #pragma unroll
        for (int nt = 0; nt < 8; ++nt) m = fmaxf(m, fmaxf(acc[nt][h*2], acc[nt][h*2+1]));
        m = fmaxf(m, __shfl_xor_sync(0xffffffffu, m, 1));
        m = fmaxf(m, __shfl_xor_sync(0xffffffffu, m, 2));
        float s = 0.f; float e[16];
        #pragma unroll
        for (int nt = 0; nt < 8; ++nt) {
            e[nt*2]   = __expf(acc[nt][h*2]   - m);
            e[nt*2+1] = __expf(acc[nt][h*2+1] - m);
            s += e[nt*2] + e[nt*2+1];
        }
        s += __shfl_xor_sync(0xffffffffu, s, 1);
        s += __shfl_xor_sync(0xffffffffu, s, 2);
        float inv = 1.f/s;
        int row = r0 + warp*16 + q + h*8;
        #pragma unroll
        for (int nt = 0; nt < 8; ++nt)
            *(float2*)&S[(long)row*64 + nt*8 + r4*2] =
                make_float2(e[nt*2]*inv, e[nt*2+1]*inv);
    }
}

// ---------------- SIMT SGEMM for the small pooled-graph GEMMs ----------------
__global__ __launch_bounds__(256) void sgemm2(
    const float* __restrict__ X0, int ld0, int d0,
    const float* __restrict__ X1, int ld1,
    const float* __restrict__ W, int ldw,
    const float* __restrict__ bias,
    float* __restrict__ Y, int ldy, int K, int relu)
{
    __shared__ float As[8][128];
    __shared__ float Bs[8][128];
    int tid = threadIdx.x;
    int tx = tid & 15, ty = tid >> 4;
    int rbase = blockIdx.x * 128;
    int cbase = blockIdx.y * 128;
    float acc[8][8];
    #pragma unroll
    for (int i = 0; i < 8; ++i)
        #pragma unroll
        for (int j = 0; j < 8; ++j) acc[i][j] = 0.f;
    int arow = tid >> 1, ak0 = (tid & 1)*4, bk = tid >> 5, bc = (tid & 31)*4;
    for (int k0 = 0; k0 < K; k0 += 8) {
        int row = rbase + arow;
        #pragma unroll
        for (int i = 0; i < 4; ++i) {
            int k = k0 + ak0 + i;
            As[ak0+i][arow] = (k < d0) ? X0[(long)row*ld0 + k] : X1[(long)row*ld1 + (k-d0)];
        }
        *(float4*)&Bs[bk][bc] = *(const float4*)&W[(long)(k0+bk)*ldw + cbase + bc];
        __syncthreads();
        #pragma unroll
        for (int kk = 0; kk < 8; ++kk) {
            float4 a0 = *(const float4*)&As[kk][ty*8];
            float4 a1 = *(const float4*)&As[kk][ty*8+4];
            float4 b0 = *(const float4*)&Bs[kk][tx*8];
            float4 b1 = *(const float4*)&Bs[kk][tx*8+4];
            float a[8]={a0.x,a0.y,a0.z,a0.w,a1.x,a1.y,a1.z,a1.w};
            float b[8]={b0.x,b0.y,b0.z,b0.w,b1.x,b1.y,b1.z,b1.w};
            #pragma unroll
            for (int i=0;i<8;++i)
                #pragma unroll
                for (int j=0;j<8;++j) acc[i][j] += a[i]*b[j];
        }
        __syncthreads();
    }
    #pragma unroll
    for (int i = 0; i < 8; ++i) {
        int row = rbase + ty*8 + i;
        #pragma unroll
        for (int j = 0; j < 8; ++j) {
            int col = cbase + tx*8 + j;
            float v = acc[i][j] + bias[col];
            if (relu) v = fmaxf(v, 0.f);
            Y[(long)row*ldy + col] = v;
        }
    }
}

// ---------------- per-graph S^T @ X ----------------
__global__ __launch_bounds__(256) void atb64(
    const float* __restrict__ Sp, const float* __restrict__ X, int ldx,
    float* __restrict__ O, int ldo)
{
    int b = blockIdx.y; int d0 = blockIdx.x*64;
    __shared__ float Ss[32][64];
    __shared__ float Xs[32][64];
    int tid = threadIdx.x;
    int tx = tid & 15, ty = tid >> 4;
    float acc[4][4];
    #pragma unroll
    for (int i=0;i<4;++i) for (int j=0;j<4;++j) acc[i][j]=0.f;
    for (int n0 = 0; n0 < 512; n0 += 32) {
        #pragma unroll
        for (int i = 0; i < 8; ++i) {
            int e = tid + i*256; int n = e>>6, k = e&63;
            int row = b*512 + n0 + n;
            Ss[n][k] = Sp[(long)row*64 + k];
            Xs[n][k] = X[(long)row*ldx + d0 + k];
        }
        __syncthreads();
        #pragma unroll
        for (int n = 0; n < 32; ++n) {
            float4 av = *(const float4*)&Ss[n][ty*4];
            float4 bv = *(const float4*)&Xs[n][tx*4];
            float a[4]={av.x,av.y,av.z,av.w};
            float bb[4]={bv.x,bv.y,bv.z,bv.w};
            #pragma unroll
            for (int i=0;i<4;++i)
                #pragma unroll
                for (int j=0;j<4;++j) acc[i][j] += a[i]*bb[j];
        }
        __syncthreads();
    }
    #pragma unroll
    for (int i = 0; i < 4; ++i) {
        int k = ty*4 + i;
        #pragma unroll
        for (int j = 0; j < 4; ++j)
            O[(long)(b*64+k)*ldo + d0 + tx*4 + j] = acc[i][j];
    }
}

__global__ void rowsum_k() {
    int i = blockIdx.x*blockDim.x + threadIdx.x;
    float s = 0.f;
    #pragma unroll 8
    for (int l = 0; l < 64; ++l) s += g_adjb[i*64 + l];
    g_dinvd[i] = 1.f / (s + 1e-9f);
}

__global__ __launch_bounds__(256) void adjmm(
    const float* __restrict__ H, int ldh, float* __restrict__ O, int ldo)
{
    int b = blockIdx.y; int d0 = blockIdx.x*64;
    __shared__ float Aj[64][65];
    __shared__ float Hs[64][65];
    int tid = threadIdx.x;
    #pragma unroll
    for (int i = 0; i < 16; ++i) {
        int e = tid + i*256; int u = e>>6, v = e&63;
        Aj[u][v] = g_adjb[b*4096 + e];
        Hs[u][v] = H[(long)(b*64+u)*ldh + d0 + v];
    }
    __syncthreads();
    int u = tid & 63, dg = tid >> 6;
    float acc[16];
    #pragma unroll
    for (int i = 0; i < 16; ++i) acc[i] = 0.f;
    for (int v = 0; v < 64; ++v) {
        float a = Aj[u][v];
        #pragma unroll
        for (int i = 0; i < 16; ++i) acc[i] += a * Hs[v][dg*16+i];
    }
    float s = g_dinvd[b*64 + u];
    #pragma unroll
    for (int i = 0; i < 16; ++i)
        O[(long)(b*64+u)*ldo + d0 + dg*16 + i] = acc[i]*s;
}

__global__ void maxpool(const float* __restrict__ X, int ld, int R, int D,
                        float* __restrict__ Y, int ldy) {
    int b = blockIdx.x;
    int d = blockIdx.y*blockDim.x + threadIdx.x;
    if (d >= D) return;
    const float* p = X + (long)b*R*ld + d;
    float m = -3.402823466e38f;
    for (int r = 0; r < R; ++r) m = fmaxf(m, p[(long)r*ld]);
    Y[(long)b*ldy + d] = m;
}

__global__ void mlp1k(const float* __restrict__ X, const float* __restrict__ W,
                      const float* __restrict__ b, float* __restrict__ Y) {
    int row = blockIdx.x, c = threadIdx.x;
    float acc = b[c];
    for (int k = 0; k < 1536; ++k) acc += X[row*1536 + k] * W[k*256 + c];
    Y[row*256 + c] = acc;
}
__global__ void mlp2k(const float* __restrict__ X, const float* __restrict__ W,
                      const float* __restrict__ b, float* __restrict__ Y) {
    int i = threadIdx.x;
    if (i >= 320) return;
    int r = i/10, j = i%10;
    float acc = b[j];
    for (int k = 0; k < 256; ++k) acc += X[r*256 + k] * W[k*10 + j];
    Y[i] = acc;
}

// ---------------- launch ----------------
extern "C" void kernel_launch(void* const* d_in, const int* in_sizes, int n_in,
                              void* d_out, int out_size) {
    const float* feat = (const float*)d_in[0];
    const int*   esrc = (const int*)  d_in[1];
    const float *W1=(const float*)d_in[3],  *b1=(const float*)d_in[4];
    const float *W2=(const float*)d_in[5],  *b2=(const float*)d_in[6];
    const float *W3=(const float*)d_in[7],  *b3=(const float*)d_in[8];
    const float *aW1=(const float*)d_in[9], *ab1=(const float*)d_in[10];
    const float *aW2=(const float*)d_in[11],*ab2=(const float*)d_in[12];
    const float *aW3=(const float*)d_in[13],*ab3=(const float*)d_in[14];
    const float *pW=(const float*)d_in[15], *pb=(const float*)d_in[16];
    const float *qW1=(const float*)d_in[17],*qb1=(const float*)d_in[18];
    const float *qW2=(const float*)d_in[19],*qb2=(const float*)d_in[20];
    const float *qW3=(const float*)d_in[21],*qb3=(const float*)d_in[22];
    const float *mW1=(const float*)d_in[23],*mb1=(const float*)d_in[24];
    const float *mW2=(const float*)d_in[25],*mb2=(const float*)d_in[26];

    static float *ecat=nullptr, *a1f, *a2f, *S, *AS, *hpool, *hnpool, *adjp,
                 *pcat, *pn, *outb, *t1;
    static bf16 *fh,*fl,*hnh,*hnl,*eh,*el,*ach,*acl;
    static bf16 *W1h,*W1l,*W2h,*W2l,*W3h,*W3l,*aW1h,*aW1l,*aW2h,*aW2l,*aW3h,*aW3l,*pWh,*pWl;
    if (!ecat) {
        cudaGetSymbolAddress((void**)&ecat,  g_ecat);
        cudaGetSymbolAddress((void**)&a1f,   g_a1f);
        cudaGetSymbolAddress((void**)&a2f,   g_a2f);
        cudaGetSymbolAddress((void**)&S,     g_Sb);
        cudaGetSymbolAddress((void**)&AS,    g_ASb);
        cudaGetSymbolAddress((void**)&hpool, g_hpool);
        cudaGetSymbolAddress((void**)&hnpool,g_hnpool);
        cudaGetSymbolAddress((void**)&adjp,  g_adjb);
        cudaGetSymbolAddress((void**)&pcat,  g_pcat);
        cudaGetSymbolAddress((void**)&pn,    g_pnb);
        cudaGetSymbolAddress((void**)&outb,  g_outb);
        cudaGetSymbolAddress((void**)&t1,    g_t1b);
        cudaGetSymbolAddress((void**)&fh, g_fh);   cudaGetSymbolAddress((void**)&fl, g_fl);
        cudaGetSymbolAddress((void**)&hnh,g_hnh);  cudaGetSymbolAddress((void**)&hnl,g_hnl);
        cudaGetSymbolAddress((void**)&eh, g_eh);   cudaGetSymbolAddress((void**)&el, g_el);
        cudaGetSymbolAddress((void**)&ach,g_ach);  cudaGetSymbolAddress((void**)&acl,g_acl);
        cudaGetSymbolAddress((void**)&W1h,g_W1h);  cudaGetSymbolAddress((void**)&W1l,g_W1l);
        cudaGetSymbolAddress((void**)&W2h,g_W2h);  cudaGetSymbolAddress((void**)&W2l,g_W2l);
        cudaGetSymbolAddress((void**)&W3h,g_W3h);  cudaGetSymbolAddress((void**)&W3l,g_W3l);
        cudaGetSymbolAddress((void**)&aW1h,g_aW1h);cudaGetSymbolAddress((void**)&aW1l,g_aW1l);
        cudaGetSymbolAddress((void**)&aW2h,g_aW2h);cudaGetSymbolAddress((void**)&aW2l,g_aW2l);
        cudaGetSymbolAddress((void**)&aW3h,g_aW3h);cudaGetSymbolAddress((void**)&aW3l,g_aW3l);
        cudaGetSymbolAddress((void**)&pWh,g_pWh);  cudaGetSymbolAddress((void**)&pWl,g_pWl);
    }

    const float inv16 = 1.f/16.f;
    auto split = [&](const float* x, bf16* h, bf16* l, int n) {
        int n4 = n/4;
        splitv4<<<(n4+255)/256, 256>>>(x, h, l, n4);
    };
    // weight + feature splits
    split(W1,  W1h,  W1l,  65536);
    split(W2,  W2h,  W2l,  131072);
    split(W3,  W3h,  W3l,  131072);
    split(aW1, aW1h, aW1l, 65536);
    split(aW2, aW2h, aW2l, 131072);
    split(aW3, aW3h, aW3l, 1048576);
    split(pW,  pWh,  pWl,  5242880);
    split(feat, fh, fl, 16384*128);

    // --- pre-pool GC stack + assignment stack (tensor cores) ---
    agg16_split<<<16384,128>>>(feat,128,32, esrc, hnh,hnl,128, inv16);
    bgemm<<<dim3(128,2),256>>>(fh,fl,128,128, hnh,hnl,128, W1h,W1l,256,  b1,
                               ecat,768, eh,el,512, 256, 1);                       // h1
    bgemm<<<dim3(128,2),256>>>(fh,fl,128,128, hnh,hnl,128, aW1h,aW1l,256, ab1,
                               a1f,256, ach,acl,2560, 256, 1);                     // a1
    agg16_split<<<16384,128>>>(ecat,768,64, esrc, hnh,hnl,256, inv16);
    bgemm<<<dim3(128,2),256>>>(eh,el,512,256, hnh,hnl,256, W2h,W2l,256, b2,
                               ecat+256,768, eh+256,el+256,512, 512, 1);           // h2
    agg16_split<<<16384,128>>>(ecat+256,768,64, esrc, hnh,hnl,256, inv16);
    bgemm<<<dim3(128,2),256>>>(eh+256,el+256,512,256, hnh,hnl,256, W3h,W3l,256, b3,
                               ecat+512,768, (bf16*)nullptr,(bf16*)nullptr,0, 512, 0); // h3
    agg16_split<<<16384,128>>>(a1f,256,64, esrc, hnh,hnl,256, inv16);
    bgemm<<<dim3(128,2),256>>>(ach,acl,2560,256, hnh,hnl,256, aW2h,aW2l,256, ab2,
                               a2f,256, ach+256,acl+256,2560, 512, 1);             // a2
    agg16_split<<<16384,128>>>(a2f,256,64, esrc, hnh,hnl,256, inv16);
    bgemm<<<dim3(128,16),256>>>(ach+256,acl+256,2560,256, hnh,hnl,256, aW3h,aW3l,2048, ab3,
                               (float*)nullptr,0, ach+512,acl+512,2560, 512, 1);   // a3

    // --- block-diagonal logits + fused masked softmax ---
    logits_mma<<<dim3(4,32),256>>>(ach, acl, pWh, pWl, pb, S);

    // --- readout 1 ---
    maxpool<<<dim3(32,3),256>>>(ecat,768, 512, 768, outb, 1536);

    // --- pooling: h_pool = S^T X, AS, adj = S^T AS ---
    atb64<<<dim3(12,32),256>>>(S, ecat,768, hpool,768);
    agg16<<<16384,64>>>(S,64,16, esrc, AS,64, 1.f);
    atb64<<<dim3(1,32),256>>>(S, AS,64, adjp,64);
    rowsum_k<<<8,256>>>();

    // --- dense SAGE stack on pooled graph (SIMT; small) ---
    adjmm<<<dim3(12,32),256>>>(hpool,768, hnpool,768);
    sgemm2<<<dim3(16,2),256>>>(hpool,768,768, hnpool,768, qW1,256, qb1, pcat,     768, 1536, 1);
    adjmm<<<dim3(4,32),256>>>(pcat,768, pn,256);
    sgemm2<<<dim3(16,2),256>>>(pcat,768,256, pn,256, qW2,256, qb2, pcat+256, 768, 512, 1);
    adjmm<<<dim3(4,32),256>>>(pcat+256,768, pn,256);
    sgemm2<<<dim3(16,2),256>>>(pcat+256,768,256, pn,256, qW3,256, qb3, pcat+512, 768, 512, 0);

    // --- readout 2 + prediction MLP ---
    maxpool<<<dim3(32,3),256>>>(pcat,768, 64, 768, outb+768, 1536);
    mlp1k<<<32,256>>>(outb, mW1, mb1, t1);
    mlp2k<<<1,320>>>(t1, mW2, mb2, (float*)d_out);
}